// round 6
// baseline (speedup 1.0000x reference)
#include <cuda_runtime.h>
#include <math.h>
#include <stdint.h>

// Problem constants
#define BB 16          // batch
#define SS 4096        // sequence
#define DD 64          // head dim
#define HH 8           // n_hashes
#define NB 64          // buckets per hash
#define NROT 32        // n_buckets/2 rotation outputs
#define TBK 512        // total buckets per batch (HH*NB)
#define CHUNKS 512     // sorted chunks per batch
#define BSZ 64         // bucket/chunk size
#define KEYS 128       // keys per chunk (own + look-back)
#define TOT (HH*SS)    // 32768 sorted entries per batch

// ---- packed f32x2 helpers: each lane is an exact scalar fp32 fma.
__device__ __forceinline__ uint64_t ffma2(uint64_t a, uint64_t b, uint64_t c) {
    uint64_t d;
    asm("fma.rn.f32x2 %0,%1,%2,%3;" : "=l"(d) : "l"(a), "l"(b), "l"(c));
    return d;
}
__device__ __forceinline__ uint64_t pack2(float x) {
    uint64_t r; uint32_t b = __float_as_uint(x);
    asm("mov.b64 %0,{%1,%1};" : "=l"(r) : "r"(b));
    return r;
}
__device__ __forceinline__ void unpack2(uint64_t p, float& a, float& b) {
    uint32_t lo, hi;
    asm("mov.b64 {%0,%1},%2;" : "=r"(lo), "=r"(hi) : "l"(p));
    a = __uint_as_float(lo); b = __uint_as_float(hi);
}

// ---------------- scratch (device globals; zero-initialized at load) ---------
__device__ int   g_buckets[BB*TOT];
__device__ int   g_hist[BB*TBK];
__device__ int   g_off[BB*TBK];
__device__ int   g_tick[BB*TOT];
__device__ float g_logits[BB*TOT];
__device__ float g_o[(size_t)BB*TOT*DD];     // per-hash outputs, 128 MB

// ---------------- k_zero: re-zero histogram AFTER scan consumed it ----------
__global__ void k_zero() {
    int i = blockIdx.x * blockDim.x + threadIdx.x;
    if (i < BB*TBK) g_hist[i] = 0;
}

// ---------------- kernel 1: LSH hashing (exact sequential chains over f) -----
__global__ void __launch_bounds__(256) k_hash(const float* __restrict__ qk,
                                              const float* __restrict__ rot) {
    extern __shared__ float srot[];          // [D][H][NROT] = 16384 floats
    for (int i = threadIdx.x; i < DD*HH*NROT; i += blockDim.x) srot[i] = rot[i];
    __syncthreads();

    int g = blockIdx.x * blockDim.x + threadIdx.x;  // global token (b*S + t)
    int b = g >> 12;
    int t = g & (SS - 1);

    float q[DD];
    const float4* qp = (const float4*)(qk + (size_t)g * DD);
#pragma unroll
    for (int i = 0; i < 16; i++) {
        float4 x = qp[i];
        q[4*i] = x.x; q[4*i+1] = x.y; q[4*i+2] = x.z; q[4*i+3] = x.w;
    }

    for (int h = 0; h < HH; h++) {
        uint64_t acc[16];
#pragma unroll
        for (int p = 0; p < 16; p++) acc[p] = 0ull;
#pragma unroll 2
        for (int f = 0; f < DD; f++) {
            uint64_t q2 = pack2(q[f]);
            const ulonglong2* rp = (const ulonglong2*)(srot + f*(HH*NROT) + h*NROT);
#pragma unroll
            for (int u = 0; u < 8; u++) {
                ulonglong2 rr = rp[u];                 // broadcast LDS.128
                acc[2*u]   = ffma2(q2, rr.x, acc[2*u]);
                acc[2*u+1] = ffma2(q2, rr.y, acc[2*u+1]);
            }
        }
        float bv = -INFINITY; int bi = 0;
#pragma unroll
        for (int p = 0; p < 16; p++) {
            float d0, d1; unpack2(acc[p], d0, d1);
            int i0 = 2*p;
            if (d0 > bv || (d0 == bv && i0 < bi)) { bv = d0; bi = i0; }
            float n0 = -d0; int m0 = NROT + i0;
            if (n0 > bv || (n0 == bv && m0 < bi)) { bv = n0; bi = m0; }
            int i1 = 2*p + 1;
            if (d1 > bv || (d1 == bv && i1 < bi)) { bv = d1; bi = i1; }
            float n1 = -d1; int m1 = NROT + i1;
            if (n1 > bv || (n1 == bv && m1 < bi)) { bv = n1; bi = m1; }
        }
        int bucket = bi + h * NB;
        g_buckets[b*TOT + h*SS + t] = bucket;
        atomicAdd(&g_hist[b*TBK + bucket], 1);
    }
}

// ---------------- kernel 2: exclusive scan of histogram (per batch) ----------
__global__ void k_scan() {
    __shared__ int s[TBK];
    int b = blockIdx.x, t = threadIdx.x;
    int myv = g_hist[b*TBK + t];
    s[t] = myv;
    __syncthreads();
    for (int o = 1; o < TBK; o <<= 1) {
        int v = (t >= o) ? s[t - o] : 0;
        __syncthreads();
        s[t] += v;
        __syncthreads();
    }
    g_off[b*TBK + t] = s[t] - myv;
}

// ---------------- kernel 3: counting-sort scatter, warp-ballot (stable) ------
__global__ void __launch_bounds__(256) k_scatter() {
    int w = (blockIdx.x * blockDim.x + threadIdx.x) >> 5;  // one warp per bucket
    if (w >= BB*TBK) return;
    int lane = threadIdx.x & 31;
    int b = w / TBK, bucket = w % TBK;
    int h = bucket >> 6;
    const int* bp = g_buckets + b*TOT + h*SS;
    int off = g_off[w];
    int* out = g_tick + b*TOT;
    int base = h * SS;
    for (int t0 = 0; t0 < SS; t0 += 32) {
        int t = t0 + lane;
        bool m = (bp[t] == bucket);
        unsigned msk = __ballot_sync(0xffffffffu, m);
        int pre = __popc(msk & ((1u << lane) - 1));
        if (m) out[off + pre] = base + t;       // ascending t => stable
        off += __popc(msk);
    }
}

// ---------------- kernel 4: chunked attention (512 threads, packed) ----------
// Shared: Qs2 [f][i] f-major, Ks[128][65], Vs[128][68], Sm[64][129].
#define KSTR 65
#define VSTR 68
#define SSTR 129
#define QS2_SZ (DD*BSZ)
#define KS_SZ  (KEYS*KSTR)
#define VS_SZ  (KEYS*VSTR)
#define SM_SZ  (BSZ*SSTR)
#define ATT_SMEM ((QS2_SZ + KS_SZ + VS_SZ + SM_SZ)*4 + KEYS*4 + BSZ*4)

__global__ void __launch_bounds__(512, 1) k_attn(const float* __restrict__ qk,
                                                 const float* __restrict__ v) {
    extern __shared__ char smraw[];
    float* Qs2 = (float*)smraw;                   // [64 f][64 i], raw q transposed
    float* Ks  = Qs2 + QS2_SZ;                    // normalized k, row-major
    float* Vs  = Ks + KS_SZ;
    float* Sm  = Vs + VS_SZ;                      // dots -> probs
    int*   tkt = (int*)(Sm + SM_SZ);              // key positions (t)
    int*   qtk = tkt + KEYS;                      // query tickers (h*S+t)

    int c = blockIdx.x, b = blockIdx.y;
    int tid = threadIdx.x;

    // ---- load: 512 threads, each owns half of one row (128B).
    //      rows 0..127 = K (rows 0..63 also queries), rows 128..255 = V.
    {
        int r    = tid >> 1;                      // 0..255
        int half = tid & 1;                       // which 32-float half
        int kr   = r & 127;                       // row within K or V set
        int src_chunk = (kr < BSZ) ? c : (c == 0 ? CHUNKS - 1 : c - 1);
        int pos = kr & (BSZ - 1);
        int ticker = g_tick[b*TOT + src_chunk*BSZ + pos];
        int t = ticker & (SS - 1);

        if (r < 128) {
            if (half == 0) {
                tkt[kr] = t;
                if (kr < BSZ) qtk[kr] = ticker;
            }
            float row[32];
            const float4* kp = (const float4*)(qk + ((size_t)b*SS + t) * DD + half*32);
#pragma unroll
            for (int i = 0; i < 8; i++) {
                float4 x = kp[i];
                row[4*i] = x.x; row[4*i+1] = x.y; row[4*i+2] = x.z; row[4*i+3] = x.w;
            }
            float ssq = 0.f;
#pragma unroll
            for (int f = 0; f < 32; f++) ssq = fmaf(row[f], row[f], ssq);
            float oth = __shfl_xor_sync(0xffffffffu, ssq, 1);
            float lo = half ? oth : ssq, hi = half ? ssq : oth;
            float nrm = sqrtf(lo + hi);           // identical in both half-threads
            float inv = 1.0f / fmaxf(nrm, 1e-12f);
#pragma unroll
            for (int f = 0; f < 32; f++) Ks[kr*KSTR + half*32 + f] = row[f] * inv;
            if (kr < BSZ) {
#pragma unroll
                for (int f = 0; f < 32; f++) Qs2[(half*32 + f)*BSZ + kr] = row[f];
            }
        } else {
            const float4* vp = (const float4*)(v + ((size_t)b*SS + t) * DD + half*32);
            float* vd = Vs + kr*VSTR + half*32;
#pragma unroll
            for (int i = 0; i < 8; i++) {
                float4 x = vp[i];
                vd[4*i] = x.x; vd[4*i+1] = x.y; vd[4*i+2] = x.z; vd[4*i+3] = x.w;
            }
        }
    }
    __syncthreads();

    // ---- phase 1: dots[i,j]. thread = (key j, query-quarter qq): 16 queries
    //      as 8 f32x2 pairs, chains over f. ----
    {
        int j  = tid & 127;
        int qq = tid >> 7;                        // 0..3
        int tj = tkt[j];
        const float* krow = Ks + j*KSTR;
        const float* qcol = Qs2 + qq*16;
        uint64_t acc[8];
#pragma unroll
        for (int p = 0; p < 8; p++) acc[p] = 0ull;
#pragma unroll 4
        for (int f = 0; f < DD; f++) {
            uint64_t k2 = pack2(krow[f]);         // conflict-free (stride 65)
            const ulonglong2* qp2 = (const ulonglong2*)(qcol + f*BSZ);
#pragma unroll
            for (int u = 0; u < 4; u++) {
                ulonglong2 qq2 = qp2[u];          // broadcast LDS.128
                acc[2*u]   = ffma2(qq2.x, k2, acc[2*u]);
                acc[2*u+1] = ffma2(qq2.y, k2, acc[2*u+1]);
            }
        }
#pragma unroll
        for (int p = 0; p < 8; p++) {
            float d0, d1; unpack2(acc[p], d0, d1);
            int i0 = qq*16 + 2*p;
            float v0 = d0 * 0.125f; if (tkt[i0]     == tj) v0 = -1e5f;
            float v1 = d1 * 0.125f; if (tkt[i0 + 1] == tj) v1 = -1e5f;
            Sm[i0*SSTR + j]       = v0;
            Sm[(i0 + 1)*SSTR + j] = v1;
        }
    }
    __syncthreads();

    // ---- phase 2: softmax, 8 threads per row (deterministic butterfly) ----
    {
        int i  = tid >> 3;
        int cq = tid & 7;
        float* row = Sm + i*SSTR + cq*16;
        float m = -INFINITY;
#pragma unroll
        for (int j = 0; j < 16; j++) m = fmaxf(m, row[j]);
        m = fmaxf(m, __shfl_xor_sync(0xffffffffu, m, 1));
        m = fmaxf(m, __shfl_xor_sync(0xffffffffu, m, 2));
        m = fmaxf(m, __shfl_xor_sync(0xffffffffu, m, 4));
        float s = 0.f;
#pragma unroll
        for (int j = 0; j < 16; j++) s += expf(row[j] - m);
        s += __shfl_xor_sync(0xffffffffu, s, 1);
        s += __shfl_xor_sync(0xffffffffu, s, 2);
        s += __shfl_xor_sync(0xffffffffu, s, 4);
        float lse = m + logf(s);
#pragma unroll
        for (int j = 0; j < 16; j++) row[j] = expf(row[j] - lse);
        if (cq == 0) g_logits[b*TOT + qtk[i]] = lse;
    }
    __syncthreads();

    // ---- phase 3: PV. thread = (query i, 8-float eighth of D). ----
    {
        int i  = tid & 63;
        int fb = (tid >> 6) * 8;
        const float* srow = Sm + i*SSTR;
        uint64_t acc[4];
#pragma unroll
        for (int p = 0; p < 4; p++) acc[p] = 0ull;
#pragma unroll 4
        for (int j = 0; j < KEYS; j++) {
            uint64_t p2 = pack2(srow[j]);         // conflict-free (stride 129)
            const ulonglong2* vp2 = (const ulonglong2*)(Vs + j*VSTR + fb);
            ulonglong2 vv = vp2[0];               // broadcast LDS.128
            acc[0] = ffma2(p2, vv.x, acc[0]);
            acc[1] = ffma2(p2, vv.y, acc[1]);
            ulonglong2 vw = vp2[1];
            acc[2] = ffma2(p2, vw.x, acc[2]);
            acc[3] = ffma2(p2, vw.y, acc[3]);
        }
        float o[8];
#pragma unroll
        for (int p = 0; p < 4; p++) unpack2(acc[p], o[2*p], o[2*p+1]);
        float* op = g_o + ((size_t)b*TOT + qtk[i]) * DD + fb;
        float4 x0 = {o[0], o[1], o[2], o[3]};
        float4 x1 = {o[4], o[5], o[6], o[7]};
        *(float4*)(op)     = x0;
        *(float4*)(op + 4) = x1;
    }
}

// ---------------- kernel 5: combine hash rounds (elementwise, fp32) ----------
__global__ void k_combine(float* __restrict__ out) {
    int idx = blockIdx.x * blockDim.x + threadIdx.x;  // over B*S*16 (float4 lanes)
    if (idx >= BB*SS*16) return;
    int q  = idx & 15;
    int bt = idx >> 4;            // b*S + t
    int b  = bt >> 12, t = bt & (SS - 1);

    const float* lp = g_logits + b*TOT + t;
    float l[HH];
    float m = -INFINITY;
#pragma unroll
    for (int h = 0; h < HH; h++) { l[h] = lp[h*SS]; m = fmaxf(m, l[h]); }
    float s = 0.f;
#pragma unroll
    for (int h = 0; h < HH; h++) { l[h] = expf(l[h] - m); s += l[h]; }
    float invs = 1.0f / s;

    float4 acc = {0.f, 0.f, 0.f, 0.f};
#pragma unroll
    for (int h = 0; h < HH; h++) {
        const float4* op = (const float4*)(g_o + ((size_t)b*TOT + h*SS + t) * DD) + q;
        float4 x = *op;
        float w = l[h] * invs;
        acc.x = fmaf(w, x.x, acc.x);
        acc.y = fmaf(w, x.y, acc.y);
        acc.z = fmaf(w, x.z, acc.z);
        acc.w = fmaf(w, x.w, acc.w);
    }
    ((float4*)out)[(size_t)bt * 16 + q] = acc;
}

// ---------------- kernel 6: buckets output (2nd tuple element) ---------------
__global__ void k_buckets(float* __restrict__ out) {
    int i = blockIdx.x * blockDim.x + threadIdx.x;
    if (i < BB*TOT) out[i] = (float)g_buckets[i];
}

// ---------------- launcher ---------------------------------------------------
// Launch order puts k_attn 4th (the slot ncu profiles). g_hist starts zeroed
// (static init) and k_zero re-zeroes it after k_scan reads it, so every call
// (correctness run and each graph replay) sees identical state.
extern "C" void kernel_launch(void* const* d_in, const int* in_sizes, int n_in,
                              void* d_out, int out_size) {
    const float* qk  = (const float*)d_in[0];
    const float* v   = (const float*)d_in[1];
    const float* rot = (const float*)d_in[2];
    float* out = (float*)d_out;

    cudaFuncSetAttribute(k_hash, cudaFuncAttributeMaxDynamicSharedMemorySize,
                         DD*HH*NROT*4);
    cudaFuncSetAttribute(k_attn, cudaFuncAttributeMaxDynamicSharedMemorySize,
                         ATT_SMEM);

    k_hash<<<BB*SS / 256, 256, DD*HH*NROT*4>>>(qk, rot);
    k_scan<<<BB, TBK>>>();
    k_scatter<<<(BB*TBK*32 + 255) / 256, 256>>>();
    dim3 ag(CHUNKS, BB);
    k_attn<<<ag, 512, ATT_SMEM>>>(qk, v);
    k_zero<<<(BB*TBK + 255) / 256, 256>>>();
    k_combine<<<(BB*SS*16 + 255) / 256, 256>>>(out);
    if (out_size >= BB*SS*DD + BB*TOT) {
        k_buckets<<<(BB*TOT + 255) / 256, 256>>>(out + (size_t)BB*SS*DD);
    }
}

// round 7
// speedup vs baseline: 1.1169x; 1.1169x over previous
#include <cuda_runtime.h>
#include <math.h>
#include <stdint.h>

// Problem constants
#define BB 16          // batch
#define SS 4096        // sequence
#define DD 64          // head dim
#define HH 8           // n_hashes
#define NB 64          // buckets per hash
#define NROT 32        // n_buckets/2 rotation outputs
#define TBK 512        // total buckets per batch (HH*NB)
#define CHUNKS 512     // sorted chunks per batch
#define BSZ 64         // bucket/chunk size
#define KEYS 128       // keys per chunk (own + look-back)
#define TOT (HH*SS)    // 32768 sorted entries per batch

// ---- packed f32x2 helpers: each lane is an exact scalar fp32 fma.
__device__ __forceinline__ uint64_t ffma2(uint64_t a, uint64_t b, uint64_t c) {
    uint64_t d;
    asm("fma.rn.f32x2 %0,%1,%2,%3;" : "=l"(d) : "l"(a), "l"(b), "l"(c));
    return d;
}
__device__ __forceinline__ uint64_t pack2(float x) {
    uint64_t r; uint32_t b = __float_as_uint(x);
    asm("mov.b64 %0,{%1,%1};" : "=l"(r) : "r"(b));
    return r;
}
__device__ __forceinline__ void unpack2(uint64_t p, float& a, float& b) {
    uint32_t lo, hi;
    asm("mov.b64 {%0,%1},%2;" : "=r"(lo), "=r"(hi) : "l"(p));
    a = __uint_as_float(lo); b = __uint_as_float(hi);
}

// ---------------- scratch (device globals; zero-initialized at load) ---------
__device__ int   g_buckets[BB*TOT];
__device__ int   g_hist[BB*TBK];
__device__ int   g_off[BB*TBK];
__device__ int   g_tick[BB*TOT];
__device__ float g_logits[BB*TOT];
__device__ float g_o[(size_t)BB*TOT*DD];     // per-hash outputs, 128 MB

// ---------------- k_zero: re-zero histogram AFTER scan consumed it ----------
__global__ void k_zero() {
    int i = blockIdx.x * blockDim.x + threadIdx.x;
    if (i < BB*TBK) g_hist[i] = 0;
}

// ---------------- kernel 1: LSH hashing (exact sequential chains over f) -----
__global__ void __launch_bounds__(256) k_hash(const float* __restrict__ qk,
                                              const float* __restrict__ rot) {
    extern __shared__ float srot[];          // [D][H][NROT] = 16384 floats
    for (int i = threadIdx.x; i < DD*HH*NROT; i += blockDim.x) srot[i] = rot[i];
    __syncthreads();

    int g = blockIdx.x * blockDim.x + threadIdx.x;  // global token (b*S + t)
    int b = g >> 12;
    int t = g & (SS - 1);

    float q[DD];
    const float4* qp = (const float4*)(qk + (size_t)g * DD);
#pragma unroll
    for (int i = 0; i < 16; i++) {
        float4 x = qp[i];
        q[4*i] = x.x; q[4*i+1] = x.y; q[4*i+2] = x.z; q[4*i+3] = x.w;
    }

    for (int h = 0; h < HH; h++) {
        uint64_t acc[16];
#pragma unroll
        for (int p = 0; p < 16; p++) acc[p] = 0ull;
#pragma unroll 2
        for (int f = 0; f < DD; f++) {
            uint64_t q2 = pack2(q[f]);
            const ulonglong2* rp = (const ulonglong2*)(srot + f*(HH*NROT) + h*NROT);
#pragma unroll
            for (int u = 0; u < 8; u++) {
                ulonglong2 rr = rp[u];                 // broadcast LDS.128
                acc[2*u]   = ffma2(q2, rr.x, acc[2*u]);
                acc[2*u+1] = ffma2(q2, rr.y, acc[2*u+1]);
            }
        }
        float bv = -INFINITY; int bi = 0;
#pragma unroll
        for (int p = 0; p < 16; p++) {
            float d0, d1; unpack2(acc[p], d0, d1);
            int i0 = 2*p;
            if (d0 > bv || (d0 == bv && i0 < bi)) { bv = d0; bi = i0; }
            float n0 = -d0; int m0 = NROT + i0;
            if (n0 > bv || (n0 == bv && m0 < bi)) { bv = n0; bi = m0; }
            int i1 = 2*p + 1;
            if (d1 > bv || (d1 == bv && i1 < bi)) { bv = d1; bi = i1; }
            float n1 = -d1; int m1 = NROT + i1;
            if (n1 > bv || (n1 == bv && m1 < bi)) { bv = n1; bi = m1; }
        }
        int bucket = bi + h * NB;
        g_buckets[b*TOT + h*SS + t] = bucket;
        atomicAdd(&g_hist[b*TBK + bucket], 1);
    }
}

// ---------------- kernel 2: exclusive scan of histogram (per batch) ----------
__global__ void k_scan() {
    __shared__ int s[TBK];
    int b = blockIdx.x, t = threadIdx.x;
    int myv = g_hist[b*TBK + t];
    s[t] = myv;
    __syncthreads();
    for (int o = 1; o < TBK; o <<= 1) {
        int v = (t >= o) ? s[t - o] : 0;
        __syncthreads();
        s[t] += v;
        __syncthreads();
    }
    g_off[b*TBK + t] = s[t] - myv;
}

// ---------------- kernel 3: counting-sort scatter, warp-ballot (stable) ------
__global__ void __launch_bounds__(256) k_scatter() {
    int w = (blockIdx.x * blockDim.x + threadIdx.x) >> 5;  // one warp per bucket
    if (w >= BB*TBK) return;
    int lane = threadIdx.x & 31;
    int b = w / TBK, bucket = w % TBK;
    int h = bucket >> 6;
    const int* bp = g_buckets + b*TOT + h*SS;
    int off = g_off[w];
    int* out = g_tick + b*TOT;
    int base = h * SS;
    for (int t0 = 0; t0 < SS; t0 += 32) {
        int t = t0 + lane;
        bool m = (bp[t] == bucket);
        unsigned msk = __ballot_sync(0xffffffffu, m);
        int pre = __popc(msk & ((1u << lane) - 1));
        if (m) out[off + pre] = base + t;       // ascending t => stable
        off += __popc(msk);
    }
}

// ---------------- kernel 4: chunked attention (register-tiled outer product) -
// Layouts (all f-/j-major so matmul phases read contiguous vectors):
//   Qs2 [f=64][i=64]   raw queries, transposed
//   Ks2 [f=64][j=128]  normalized keys, transposed
//   Vs  [j=128][d=64]  row-major
//   Smt [j=128][i=68-stride]  scores TRANSPOSED (i-pairs contiguous for PV)
#define QSTR2 64
#define KSTR2 128
#define VSTR2 64
#define SMTSTR 68
#define QS2_SZ (DD*QSTR2)
#define KS2_SZ (DD*KSTR2)
#define VS_SZ  (KEYS*VSTR2)
#define SMT_SZ (KEYS*SMTSTR)
#define ATT_SMEM ((QS2_SZ + KS2_SZ + VS_SZ + SMT_SZ)*4 + KEYS*4 + BSZ*4)

__global__ void __launch_bounds__(512, 1) k_attn(const float* __restrict__ qk,
                                                 const float* __restrict__ v) {
    extern __shared__ char smraw[];
    float* Qs2 = (float*)smraw;
    float* Ks2 = Qs2 + QS2_SZ;
    float* Vs  = Ks2 + KS2_SZ;
    float* Smt = Vs + VS_SZ;
    int*   tkt = (int*)(Smt + SMT_SZ);            // key positions (t)
    int*   qtk = tkt + KEYS;                      // query tickers (h*S+t)

    int c = blockIdx.x, b = blockIdx.y;
    int tid = threadIdx.x;

    // ---- load: 512 threads, each owns half of one row (128B).
    //      rows 0..127 = K (rows 0..63 also queries), rows 128..255 = V.
    {
        int r    = tid >> 1;                      // 0..255
        int half = tid & 1;                       // which 32-float half
        int kr   = r & 127;
        int src_chunk = (kr < BSZ) ? c : (c == 0 ? CHUNKS - 1 : c - 1);
        int pos = kr & (BSZ - 1);
        int ticker = g_tick[b*TOT + src_chunk*BSZ + pos];
        int t = ticker & (SS - 1);

        if (r < 128) {
            if (half == 0) {
                tkt[kr] = t;
                if (kr < BSZ) qtk[kr] = ticker;
            }
            float row[32];
            const float4* kp = (const float4*)(qk + ((size_t)b*SS + t) * DD + half*32);
#pragma unroll
            for (int i = 0; i < 8; i++) {
                float4 x = kp[i];
                row[4*i] = x.x; row[4*i+1] = x.y; row[4*i+2] = x.z; row[4*i+3] = x.w;
            }
            float ssq = 0.f;
#pragma unroll
            for (int f = 0; f < 32; f++) ssq = fmaf(row[f], row[f], ssq);
            float oth = __shfl_xor_sync(0xffffffffu, ssq, 1);
            float lo = half ? oth : ssq, hi = half ? ssq : oth;
            float nrm = sqrtf(lo + hi);           // identical in both half-threads
            float inv = 1.0f / fmaxf(nrm, 1e-12f);
#pragma unroll
            for (int f = 0; f < 32; f++) Ks2[(half*32 + f)*KSTR2 + kr] = row[f] * inv;
            if (kr < BSZ) {
#pragma unroll
                for (int f = 0; f < 32; f++) Qs2[(half*32 + f)*QSTR2 + kr] = row[f];
            }
        } else {
            const float4* vp = (const float4*)(v + ((size_t)b*SS + t) * DD + half*32);
            float* vd = Vs + kr*VSTR2 + half*32;
#pragma unroll
            for (int i = 0; i < 8; i++) {
                float4 x = vp[i];
                vd[4*i] = x.x; vd[4*i+1] = x.y; vd[4*i+2] = x.z; vd[4*i+3] = x.w;
            }
        }
    }
    __syncthreads();

    // ---- phase 1: dots, 4x4 register tile per thread (outer product over f).
    //      Each output is a sequential fma chain over f (rounding preserved).
    {
        int it = tid & 15;                        // i-tile: i0 = 4*it
        int jt = tid >> 4;                        // j-tile: j0 = 4*jt
        int i0 = it * 4, j0 = jt * 4;
        uint64_t a0[4], a1[4];                    // [j] x (i0,i0+1) / (i0+2,i0+3)
#pragma unroll
        for (int u = 0; u < 4; u++) { a0[u] = 0ull; a1[u] = 0ull; }
#pragma unroll 2
        for (int f = 0; f < DD; f++) {
            ulonglong2 qq = *(const ulonglong2*)(Qs2 + f*QSTR2 + i0);
            float4 kk = *(const float4*)(Ks2 + f*KSTR2 + j0);
            uint64_t k0 = pack2(kk.x), k1 = pack2(kk.y);
            uint64_t k2 = pack2(kk.z), k3 = pack2(kk.w);
            a0[0] = ffma2(qq.x, k0, a0[0]); a1[0] = ffma2(qq.y, k0, a1[0]);
            a0[1] = ffma2(qq.x, k1, a0[1]); a1[1] = ffma2(qq.y, k1, a1[1]);
            a0[2] = ffma2(qq.x, k2, a0[2]); a1[2] = ffma2(qq.y, k2, a1[2]);
            a0[3] = ffma2(qq.x, k3, a0[3]); a1[3] = ffma2(qq.y, k3, a1[3]);
        }
        int tki[4], tkj[4];
#pragma unroll
        for (int u = 0; u < 4; u++) { tki[u] = tkt[i0+u]; tkj[u] = tkt[j0+u]; }
#pragma unroll
        for (int u = 0; u < 4; u++) {
            float d0, d1, d2, d3;
            unpack2(a0[u], d0, d1);
            unpack2(a1[u], d2, d3);
            int tj = tkj[u];
            float4 x;
            x.x = (tki[0] == tj) ? -1e5f : d0 * 0.125f;
            x.y = (tki[1] == tj) ? -1e5f : d1 * 0.125f;
            x.z = (tki[2] == tj) ? -1e5f : d2 * 0.125f;
            x.w = (tki[3] == tj) ? -1e5f : d3 * 0.125f;
            *(float4*)(Smt + (j0+u)*SMTSTR + i0) = x;   // transposed store
        }
    }
    __syncthreads();

    // ---- phase 2: softmax over j per row i; 8 lanes/row, j interleaved by 8
    //      (bank = (4*cq + i) & 31 -> conflict-free). ----
    {
        int i  = tid >> 3;
        int cq = tid & 7;
        float m = -INFINITY;
#pragma unroll
        for (int jj = 0; jj < 16; jj++)
            m = fmaxf(m, Smt[(cq + 8*jj)*SMTSTR + i]);
        m = fmaxf(m, __shfl_xor_sync(0xffffffffu, m, 1));
        m = fmaxf(m, __shfl_xor_sync(0xffffffffu, m, 2));
        m = fmaxf(m, __shfl_xor_sync(0xffffffffu, m, 4));
        float s = 0.f;
#pragma unroll
        for (int jj = 0; jj < 16; jj++)
            s += expf(Smt[(cq + 8*jj)*SMTSTR + i] - m);
        s += __shfl_xor_sync(0xffffffffu, s, 1);
        s += __shfl_xor_sync(0xffffffffu, s, 2);
        s += __shfl_xor_sync(0xffffffffu, s, 4);
        float lse = m + logf(s);
#pragma unroll
        for (int jj = 0; jj < 16; jj++) {
            float* p = Smt + (cq + 8*jj)*SMTSTR + i;
            *p = expf(*p - lse);
        }
        if (cq == 0) g_logits[b*TOT + qtk[i]] = lse;
    }
    __syncthreads();

    // ---- phase 3: PV, 2x4 tile (i-pair x 4 d) per thread; chain over j.
    //      LDS.64 of Smt gives the i-pair pre-packed for f32x2. ----
    {
        int dt  = tid & 15;                       // d0 = 4*dt
        int it2 = tid >> 4;                       // i = 2*it2
        int d0 = dt * 4, i0 = it2 * 2;
        uint64_t a0 = 0ull, a1 = 0ull, a2 = 0ull, a3 = 0ull;
#pragma unroll 4
        for (int j = 0; j < KEYS; j++) {
            uint64_t sp = *(const uint64_t*)(Smt + j*SMTSTR + i0);
            float4 vv = *(const float4*)(Vs + j*VSTR2 + d0);
            a0 = ffma2(sp, pack2(vv.x), a0);
            a1 = ffma2(sp, pack2(vv.y), a1);
            a2 = ffma2(sp, pack2(vv.z), a2);
            a3 = ffma2(sp, pack2(vv.w), a3);
        }
        float o0[4], o1[4];
        unpack2(a0, o0[0], o1[0]); unpack2(a1, o0[1], o1[1]);
        unpack2(a2, o0[2], o1[2]); unpack2(a3, o0[3], o1[3]);
        float4 x0 = {o0[0], o0[1], o0[2], o0[3]};
        float4 x1 = {o1[0], o1[1], o1[2], o1[3]};
        *(float4*)(g_o + ((size_t)b*TOT + qtk[i0])     * DD + d0) = x0;
        *(float4*)(g_o + ((size_t)b*TOT + qtk[i0 + 1]) * DD + d0) = x1;
    }
}

// ---------------- kernel 5: combine hash rounds (elementwise, fp32) ----------
__global__ void k_combine(float* __restrict__ out) {
    int idx = blockIdx.x * blockDim.x + threadIdx.x;  // over B*S*16 (float4 lanes)
    if (idx >= BB*SS*16) return;
    int q  = idx & 15;
    int bt = idx >> 4;            // b*S + t
    int b  = bt >> 12, t = bt & (SS - 1);

    const float* lp = g_logits + b*TOT + t;
    float l[HH];
    float m = -INFINITY;
#pragma unroll
    for (int h = 0; h < HH; h++) { l[h] = lp[h*SS]; m = fmaxf(m, l[h]); }
    float s = 0.f;
#pragma unroll
    for (int h = 0; h < HH; h++) { l[h] = expf(l[h] - m); s += l[h]; }
    float invs = 1.0f / s;

    float4 acc = {0.f, 0.f, 0.f, 0.f};
#pragma unroll
    for (int h = 0; h < HH; h++) {
        const float4* op = (const float4*)(g_o + ((size_t)b*TOT + h*SS + t) * DD) + q;
        float4 x = *op;
        float w = l[h] * invs;
        acc.x = fmaf(w, x.x, acc.x);
        acc.y = fmaf(w, x.y, acc.y);
        acc.z = fmaf(w, x.z, acc.z);
        acc.w = fmaf(w, x.w, acc.w);
    }
    ((float4*)out)[(size_t)bt * 16 + q] = acc;
}

// ---------------- kernel 6: buckets output (2nd tuple element) ---------------
__global__ void k_buckets(float* __restrict__ out) {
    int i = blockIdx.x * blockDim.x + threadIdx.x;
    if (i < BB*TOT) out[i] = (float)g_buckets[i];
}

// ---------------- launcher ---------------------------------------------------
// k_attn stays 4th (the slot ncu profiles). g_hist starts zeroed (static init)
// and k_zero re-zeroes it after k_scan reads it -> identical state every call.
extern "C" void kernel_launch(void* const* d_in, const int* in_sizes, int n_in,
                              void* d_out, int out_size) {
    const float* qk  = (const float*)d_in[0];
    const float* v   = (const float*)d_in[1];
    const float* rot = (const float*)d_in[2];
    float* out = (float*)d_out;

    cudaFuncSetAttribute(k_hash, cudaFuncAttributeMaxDynamicSharedMemorySize,
                         DD*HH*NROT*4);
    cudaFuncSetAttribute(k_attn, cudaFuncAttributeMaxDynamicSharedMemorySize,
                         ATT_SMEM);

    k_hash<<<BB*SS / 256, 256, DD*HH*NROT*4>>>(qk, rot);
    k_scan<<<BB, TBK>>>();
    k_scatter<<<(BB*TBK*32 + 255) / 256, 256>>>();
    dim3 ag(CHUNKS, BB);
    k_attn<<<ag, 512, ATT_SMEM>>>(qk, v);
    k_zero<<<(BB*TBK + 255) / 256, 256>>>();
    k_combine<<<(BB*SS*16 + 255) / 256, 256>>>(out);
    if (out_size >= BB*SS*DD + BB*TOT) {
        k_buckets<<<(BB*TOT + 255) / 256, 256>>>(out + (size_t)BB*SS*DD);
    }
}

// round 8
// speedup vs baseline: 1.2172x; 1.0898x over previous
#include <cuda_runtime.h>
#include <math.h>
#include <stdint.h>

// Problem constants
#define BB 16          // batch
#define SS 4096        // sequence
#define DD 64          // head dim
#define HH 8           // n_hashes
#define NB 64          // buckets per hash
#define NROT 32        // n_buckets/2 rotation outputs
#define TBK 512        // total buckets per batch (HH*NB)
#define CHUNKS 512     // sorted chunks per batch
#define BSZ 64         // bucket/chunk size
#define KEYS 128       // keys per chunk (own + look-back)
#define TOT (HH*SS)    // 32768 sorted entries per batch

// ---- packed f32x2 helpers: each lane is an exact scalar fp32 fma.
__device__ __forceinline__ uint64_t ffma2(uint64_t a, uint64_t b, uint64_t c) {
    uint64_t d;
    asm("fma.rn.f32x2 %0,%1,%2,%3;" : "=l"(d) : "l"(a), "l"(b), "l"(c));
    return d;
}
__device__ __forceinline__ uint64_t pack2(float x) {
    uint64_t r; uint32_t b = __float_as_uint(x);
    asm("mov.b64 %0,{%1,%1};" : "=l"(r) : "r"(b));
    return r;
}
__device__ __forceinline__ void unpack2(uint64_t p, float& a, float& b) {
    uint32_t lo, hi;
    asm("mov.b64 {%0,%1},%2;" : "=r"(lo), "=r"(hi) : "l"(p));
    a = __uint_as_float(lo); b = __uint_as_float(hi);
}

// ---------------- scratch (device globals; zero-initialized at load) ---------
__device__ int   g_buckets[BB*TOT];
__device__ int   g_hist[BB*TBK];
__device__ int   g_off[BB*TBK];
__device__ int   g_tick[BB*TOT];
__device__ float g_logits[BB*TOT];
__device__ float g_o[(size_t)BB*TOT*DD];     // per-hash outputs, 128 MB

// ---------------- k_zero: re-zero histogram AFTER scan consumed it ----------
__global__ void k_zero() {
    int i = blockIdx.x * blockDim.x + threadIdx.x;
    if (i < BB*TBK) g_hist[i] = 0;
}

// ---------------- kernel 1: LSH hashing (exact sequential chains over f) -----
__global__ void __launch_bounds__(256) k_hash(const float* __restrict__ qk,
                                              const float* __restrict__ rot) {
    extern __shared__ float srot[];          // [D][H][NROT] = 16384 floats
    for (int i = threadIdx.x; i < DD*HH*NROT; i += blockDim.x) srot[i] = rot[i];
    __syncthreads();

    int g = blockIdx.x * blockDim.x + threadIdx.x;  // global token (b*S + t)
    int b = g >> 12;
    int t = g & (SS - 1);

    float q[DD];
    const float4* qp = (const float4*)(qk + (size_t)g * DD);
#pragma unroll
    for (int i = 0; i < 16; i++) {
        float4 x = qp[i];
        q[4*i] = x.x; q[4*i+1] = x.y; q[4*i+2] = x.z; q[4*i+3] = x.w;
    }

    for (int h = 0; h < HH; h++) {
        uint64_t acc[16];
#pragma unroll
        for (int p = 0; p < 16; p++) acc[p] = 0ull;
#pragma unroll 2
        for (int f = 0; f < DD; f++) {
            uint64_t q2 = pack2(q[f]);
            const ulonglong2* rp = (const ulonglong2*)(srot + f*(HH*NROT) + h*NROT);
#pragma unroll
            for (int u = 0; u < 8; u++) {
                ulonglong2 rr = rp[u];                 // broadcast LDS.128
                acc[2*u]   = ffma2(q2, rr.x, acc[2*u]);
                acc[2*u+1] = ffma2(q2, rr.y, acc[2*u+1]);
            }
        }
        float bv = -INFINITY; int bi = 0;
#pragma unroll
        for (int p = 0; p < 16; p++) {
            float d0, d1; unpack2(acc[p], d0, d1);
            int i0 = 2*p;
            if (d0 > bv || (d0 == bv && i0 < bi)) { bv = d0; bi = i0; }
            float n0 = -d0; int m0 = NROT + i0;
            if (n0 > bv || (n0 == bv && m0 < bi)) { bv = n0; bi = m0; }
            int i1 = 2*p + 1;
            if (d1 > bv || (d1 == bv && i1 < bi)) { bv = d1; bi = i1; }
            float n1 = -d1; int m1 = NROT + i1;
            if (n1 > bv || (n1 == bv && m1 < bi)) { bv = n1; bi = m1; }
        }
        int bucket = bi + h * NB;
        g_buckets[b*TOT + h*SS + t] = bucket;
        atomicAdd(&g_hist[b*TBK + bucket], 1);
    }
}

// ---------------- kernel 2: exclusive scan of histogram (per batch) ----------
__global__ void k_scan() {
    __shared__ int s[TBK];
    int b = blockIdx.x, t = threadIdx.x;
    int myv = g_hist[b*TBK + t];
    s[t] = myv;
    __syncthreads();
    for (int o = 1; o < TBK; o <<= 1) {
        int v = (t >= o) ? s[t - o] : 0;
        __syncthreads();
        s[t] += v;
        __syncthreads();
    }
    g_off[b*TBK + t] = s[t] - myv;
}

// ---------------- kernel 3: counting-sort scatter, warp-ballot (stable) ------
__global__ void __launch_bounds__(256) k_scatter() {
    int w = (blockIdx.x * blockDim.x + threadIdx.x) >> 5;  // one warp per bucket
    if (w >= BB*TBK) return;
    int lane = threadIdx.x & 31;
    int b = w / TBK, bucket = w % TBK;
    int h = bucket >> 6;
    const int* bp = g_buckets + b*TOT + h*SS;
    int off = g_off[w];
    int* out = g_tick + b*TOT;
    int base = h * SS;
    for (int t0 = 0; t0 < SS; t0 += 32) {
        int t = t0 + lane;
        bool m = (bp[t] == bucket);
        unsigned msk = __ballot_sync(0xffffffffu, m);
        int pre = __popc(msk & ((1u << lane) - 1));
        if (m) out[off + pre] = base + t;       // ascending t => stable
        off += __popc(msk);
    }
}

// ---------------- kernel 4: chunked attention (2 CTAs/SM, norm-factored) -----
// dots[i,j] = ||q_i|| * (k̂_i · k̂_j) / 8  — queries are rows 0..63 of Ks2,
// so no separate Q tile. Layouts:
//   Ks2 [f=64][j=128]  normalized keys, transposed
//   Vs  [j=128][d=64]  row-major
//   Smt [j=128][i=68-stride]  scores TRANSPOSED (i-pairs contiguous for PV)
#define KSTR2 128
#define VSTR2 64
#define SMTSTR 68
#define KS2_SZ (DD*KSTR2)
#define VS_SZ  (KEYS*VSTR2)
#define SMT_SZ (KEYS*SMTSTR)
#define ATT_SMEM ((KS2_SZ + VS_SZ + SMT_SZ + BSZ)*4 + KEYS*4 + BSZ*4)

__global__ void __launch_bounds__(512, 2) k_attn(const float* __restrict__ qk,
                                                 const float* __restrict__ v) {
    extern __shared__ char smraw[];
    float* Ks2   = (float*)smraw;
    float* Vs    = Ks2 + KS2_SZ;
    float* Smt   = Vs + VS_SZ;
    float* norms = Smt + SMT_SZ;                  // query norms (64)
    int*   tkt   = (int*)(norms + BSZ);           // key positions (t)
    int*   qtk   = tkt + KEYS;                    // query tickers (h*S+t)

    int c = blockIdx.x, b = blockIdx.y;
    int tid = threadIdx.x;

    // ---- load: 512 threads, each owns half of one row (128B).
    //      rows 0..127 = K (rows 0..63 also queries), rows 128..255 = V.
    {
        int r    = tid >> 1;                      // 0..255
        int half = tid & 1;                       // which 32-float half
        int kr   = r & 127;
        int src_chunk = (kr < BSZ) ? c : (c == 0 ? CHUNKS - 1 : c - 1);
        int pos = kr & (BSZ - 1);
        int ticker = g_tick[b*TOT + src_chunk*BSZ + pos];
        int t = ticker & (SS - 1);

        if (r < 128) {
            if (half == 0) {
                tkt[kr] = t;
                if (kr < BSZ) qtk[kr] = ticker;
            }
            float row[32];
            const float4* kp = (const float4*)(qk + ((size_t)b*SS + t) * DD + half*32);
#pragma unroll
            for (int i = 0; i < 8; i++) {
                float4 x = kp[i];
                row[4*i] = x.x; row[4*i+1] = x.y; row[4*i+2] = x.z; row[4*i+3] = x.w;
            }
            float ssq = 0.f;
#pragma unroll
            for (int f = 0; f < 32; f++) ssq = fmaf(row[f], row[f], ssq);
            float oth = __shfl_xor_sync(0xffffffffu, ssq, 1);
            float lo = half ? oth : ssq, hi = half ? ssq : oth;
            float nrm = sqrtf(lo + hi);           // identical in both half-threads
            float inv = 1.0f / fmaxf(nrm, 1e-12f);
#pragma unroll
            for (int f = 0; f < 32; f++) Ks2[(half*32 + f)*KSTR2 + kr] = row[f] * inv;
            if (kr < BSZ && half == 0) norms[kr] = nrm;
        } else {
            const float4* vp = (const float4*)(v + ((size_t)b*SS + t) * DD + half*32);
            float* vd = Vs + kr*VSTR2 + half*32;
#pragma unroll
            for (int i = 0; i < 8; i++) {
                float4 x = vp[i];
                vd[4*i] = x.x; vd[4*i+1] = x.y; vd[4*i+2] = x.z; vd[4*i+3] = x.w;
            }
        }
    }
    __syncthreads();

    // ---- phase 1: dots, 4x4 register tile (outer product over f on Ks2). ----
    {
        int it = tid & 15;                        // i-tile: i0 = 4*it
        int jt = tid >> 4;                        // j-tile: j0 = 4*jt
        int i0 = it * 4, j0 = jt * 4;
        uint64_t a0[4], a1[4];                    // [j] x (i0,i0+1) / (i0+2,i0+3)
#pragma unroll
        for (int u = 0; u < 4; u++) { a0[u] = 0ull; a1[u] = 0ull; }
#pragma unroll 2
        for (int f = 0; f < DD; f++) {
            const float* krow = Ks2 + f*KSTR2;
            ulonglong2 qq = *(const ulonglong2*)(krow + i0);   // q̂ = k̂ cols 0..63
            float4 kk = *(const float4*)(krow + j0);
            uint64_t k0 = pack2(kk.x), k1 = pack2(kk.y);
            uint64_t k2 = pack2(kk.z), k3 = pack2(kk.w);
            a0[0] = ffma2(qq.x, k0, a0[0]); a1[0] = ffma2(qq.y, k0, a1[0]);
            a0[1] = ffma2(qq.x, k1, a0[1]); a1[1] = ffma2(qq.y, k1, a1[1]);
            a0[2] = ffma2(qq.x, k2, a0[2]); a1[2] = ffma2(qq.y, k2, a1[2]);
            a0[3] = ffma2(qq.x, k3, a0[3]); a1[3] = ffma2(qq.y, k3, a1[3]);
        }
        int tki[4], tkj[4];
        float sc[4];
#pragma unroll
        for (int u = 0; u < 4; u++) {
            tki[u] = tkt[i0+u]; tkj[u] = tkt[j0+u];
            sc[u] = norms[i0+u] * 0.125f;
        }
#pragma unroll
        for (int u = 0; u < 4; u++) {
            float d0, d1, d2, d3;
            unpack2(a0[u], d0, d1);
            unpack2(a1[u], d2, d3);
            int tj = tkj[u];
            float4 x;
            x.x = (tki[0] == tj) ? -1e5f : d0 * sc[0];
            x.y = (tki[1] == tj) ? -1e5f : d1 * sc[1];
            x.z = (tki[2] == tj) ? -1e5f : d2 * sc[2];
            x.w = (tki[3] == tj) ? -1e5f : d3 * sc[3];
            *(float4*)(Smt + (j0+u)*SMTSTR + i0) = x;   // transposed store
        }
    }
    __syncthreads();

    // ---- phase 2: softmax over j per row i; 8 lanes/row, j interleaved by 8
    //      (bank = (4*cq + i) & 31 -> conflict-free). ----
    {
        int i  = tid >> 3;
        int cq = tid & 7;
        float m = -INFINITY;
#pragma unroll
        for (int jj = 0; jj < 16; jj++)
            m = fmaxf(m, Smt[(cq + 8*jj)*SMTSTR + i]);
        m = fmaxf(m, __shfl_xor_sync(0xffffffffu, m, 1));
        m = fmaxf(m, __shfl_xor_sync(0xffffffffu, m, 2));
        m = fmaxf(m, __shfl_xor_sync(0xffffffffu, m, 4));
        float s = 0.f;
#pragma unroll
        for (int jj = 0; jj < 16; jj++)
            s += expf(Smt[(cq + 8*jj)*SMTSTR + i] - m);
        s += __shfl_xor_sync(0xffffffffu, s, 1);
        s += __shfl_xor_sync(0xffffffffu, s, 2);
        s += __shfl_xor_sync(0xffffffffu, s, 4);
        float lse = m + logf(s);
#pragma unroll
        for (int jj = 0; jj < 16; jj++) {
            float* p = Smt + (cq + 8*jj)*SMTSTR + i;
            *p = expf(*p - lse);
        }
        if (cq == 0) g_logits[b*TOT + qtk[i]] = lse;
    }
    __syncthreads();

    // ---- phase 3: PV; warp = 8 i-pairs x 4 d-quarters (64B+64B per j). ----
    {
        int ip = (tid & 7) | ((tid >> 7) << 3);   // i-pair 0..31
        int dt = (tid >> 3) & 15;                 // d-quarter 0..15
        int i0 = ip * 2, d0 = dt * 4;
        uint64_t a0 = 0ull, a1 = 0ull, a2 = 0ull, a3 = 0ull;
#pragma unroll 4
        for (int j = 0; j < KEYS; j++) {
            uint64_t sp = *(const uint64_t*)(Smt + j*SMTSTR + i0);
            float4 vv = *(const float4*)(Vs + j*VSTR2 + d0);
            a0 = ffma2(sp, pack2(vv.x), a0);
            a1 = ffma2(sp, pack2(vv.y), a1);
            a2 = ffma2(sp, pack2(vv.z), a2);
            a3 = ffma2(sp, pack2(vv.w), a3);
        }
        float o0[4], o1[4];
        unpack2(a0, o0[0], o1[0]); unpack2(a1, o0[1], o1[1]);
        unpack2(a2, o0[2], o1[2]); unpack2(a3, o0[3], o1[3]);
        float4 x0 = {o0[0], o0[1], o0[2], o0[3]};
        float4 x1 = {o1[0], o1[1], o1[2], o1[3]};
        *(float4*)(g_o + ((size_t)b*TOT + qtk[i0])     * DD + d0) = x0;
        *(float4*)(g_o + ((size_t)b*TOT + qtk[i0 + 1]) * DD + d0) = x1;
    }
}

// ---------------- kernel 5: combine hash rounds (elementwise, fp32) ----------
__global__ void k_combine(float* __restrict__ out) {
    int idx = blockIdx.x * blockDim.x + threadIdx.x;  // over B*S*16 (float4 lanes)
    if (idx >= BB*SS*16) return;
    int q  = idx & 15;
    int bt = idx >> 4;            // b*S + t
    int b  = bt >> 12, t = bt & (SS - 1);

    const float* lp = g_logits + b*TOT + t;
    float l[HH];
    float m = -INFINITY;
#pragma unroll
    for (int h = 0; h < HH; h++) { l[h] = lp[h*SS]; m = fmaxf(m, l[h]); }
    float s = 0.f;
#pragma unroll
    for (int h = 0; h < HH; h++) { l[h] = expf(l[h] - m); s += l[h]; }
    float invs = 1.0f / s;

    float4 acc = {0.f, 0.f, 0.f, 0.f};
#pragma unroll
    for (int h = 0; h < HH; h++) {
        const float4* op = (const float4*)(g_o + ((size_t)b*TOT + h*SS + t) * DD) + q;
        float4 x = *op;
        float w = l[h] * invs;
        acc.x = fmaf(w, x.x, acc.x);
        acc.y = fmaf(w, x.y, acc.y);
        acc.z = fmaf(w, x.z, acc.z);
        acc.w = fmaf(w, x.w, acc.w);
    }
    ((float4*)out)[(size_t)bt * 16 + q] = acc;
}

// ---------------- kernel 6: buckets output (2nd tuple element) ---------------
__global__ void k_buckets(float* __restrict__ out) {
    int i = blockIdx.x * blockDim.x + threadIdx.x;
    if (i < BB*TOT) out[i] = (float)g_buckets[i];
}

// ---------------- launcher ---------------------------------------------------
// k_attn stays 4th (the slot ncu profiles). g_hist starts zeroed (static init)
// and k_zero re-zeroes it after k_scan reads it -> identical state every call.
extern "C" void kernel_launch(void* const* d_in, const int* in_sizes, int n_in,
                              void* d_out, int out_size) {
    const float* qk  = (const float*)d_in[0];
    const float* v   = (const float*)d_in[1];
    const float* rot = (const float*)d_in[2];
    float* out = (float*)d_out;

    cudaFuncSetAttribute(k_hash, cudaFuncAttributeMaxDynamicSharedMemorySize,
                         DD*HH*NROT*4);
    cudaFuncSetAttribute(k_attn, cudaFuncAttributeMaxDynamicSharedMemorySize,
                         ATT_SMEM);

    k_hash<<<BB*SS / 256, 256, DD*HH*NROT*4>>>(qk, rot);
    k_scan<<<BB, TBK>>>();
    k_scatter<<<(BB*TBK*32 + 255) / 256, 256>>>();
    dim3 ag(CHUNKS, BB);
    k_attn<<<ag, 512, ATT_SMEM>>>(qk, v);
    k_zero<<<(BB*TBK + 255) / 256, 256>>>();
    k_combine<<<(BB*SS*16 + 255) / 256, 256>>>(out);
    if (out_size >= BB*SS*DD + BB*TOT) {
        k_buckets<<<(BB*TOT + 255) / 256, 256>>>(out + (size_t)BB*SS*DD);
    }
}